// round 7
// baseline (speedup 1.0000x reference)
#include <cuda_runtime.h>

// GCN: N=100000, E=1600000, 16 -> 64 -> (128->16 folded). One persistent kernel.
static constexpr int MAXN = 100000;
static constexpr int MAXE = 1600000;
static constexpr int CSRSZ = MAXE + 4 * MAXN;   // padded segments
static constexpr int NB = 148;
static constexpr int NT = 1024;

__device__ int   g_deg[MAXN];        // zero at entry (zero-init + re-zeroed each run)
__device__ float g_dinv[MAXN];
__device__ int   g_off[MAXN + 1];
__device__ int   g_cur[MAXN];
__device__ __align__(16) int g_csr[CSRSZ];
__device__ int   g_bsum[NB];
__device__ float g_xs[(MAXN + 1) * 16];   // row MAXN stays zero (sentinel)
__device__ float g_a1[MAXN * 16];
__device__ float g_z[(MAXN + 1) * 16];    // row MAXN stays zero (sentinel)
__device__ float g_w2l[64 * 16];
__device__ float g_b2l[16];
__device__ unsigned g_bar_count;
__device__ unsigned g_bar_gen;

// ---- software grid barrier (all NB blocks resident) ----
__device__ __forceinline__ void gsync() {
    __syncthreads();
    __threadfence();
    if (threadIdx.x == 0) {
        volatile unsigned* genp = &g_bar_gen;
        unsigned gen = *genp;
        if (atomicAdd(&g_bar_count, 1u) == (unsigned)(NB - 1)) {
            g_bar_count = 0;
            __threadfence();
            *genp = gen + 1;
        } else {
            while (*genp == gen) { }
        }
    }
    __syncthreads();
}

// one work item = (node, quarter j). Segments are padded to multiples of 4 with
// sentinel index (zero feature row): uniform trip count, no tail, int4 index loads.
__device__ __forceinline__ void agg16_item(const float* __restrict__ srcf,
                                           float* __restrict__ dstf,
                                           const float* __restrict__ bias, int w) {
    int node = w >> 2;
    int j = w & 3;
    int st = g_off[node];
    int nbatch = (g_off[node + 1] - st) >> 2;
    const int4* cp = (const int4*)(g_csr + st);
    const float4* s4 = (const float4*)srcf;
    float4 a0 = __ldg(&s4[node * 4 + j]);   // self term (src already dinv-scaled)
    float4 a1 = make_float4(0.f, 0.f, 0.f, 0.f);
    float4 a2 = make_float4(0.f, 0.f, 0.f, 0.f);
    float4 a3 = make_float4(0.f, 0.f, 0.f, 0.f);
    int4 idx;
    if (nbatch > 0) idx = __ldg(&cp[0]);
    for (int b = 0; b < nbatch; b++) {
        int4 nidx;
        bool more = (b + 1 < nbatch);
        if (more) nidx = __ldg(&cp[b + 1]);
        float4 v0 = __ldg(&s4[idx.x * 4 + j]);
        float4 v1 = __ldg(&s4[idx.y * 4 + j]);
        float4 v2 = __ldg(&s4[idx.z * 4 + j]);
        float4 v3 = __ldg(&s4[idx.w * 4 + j]);
        a0.x += v0.x; a0.y += v0.y; a0.z += v0.z; a0.w += v0.w;
        a1.x += v1.x; a1.y += v1.y; a1.z += v1.z; a1.w += v1.w;
        a2.x += v2.x; a2.y += v2.y; a2.z += v2.z; a2.w += v2.w;
        a3.x += v3.x; a3.y += v3.y; a3.z += v3.z; a3.w += v3.w;
        if (more) idx = nidx;
    }
    float d = __ldg(&g_dinv[node]);
    float4 r;
    r.x = d * ((a0.x + a1.x) + (a2.x + a3.x));
    r.y = d * ((a0.y + a1.y) + (a2.y + a3.y));
    r.z = d * ((a0.z + a1.z) + (a2.z + a3.z));
    r.w = d * ((a0.w + a1.w) + (a2.w + a3.w));
    if (bias) {
        float4 b = __ldg(&((const float4*)bias)[j]);
        r.x += b.x; r.y += b.y; r.z += b.z; r.w += b.w;
    }
    ((float4*)dstf)[node * 4 + j] = r;
}

__global__ void __launch_bounds__(NT, 1) uber(
    const float* __restrict__ x, const int* __restrict__ ei,
    const float* __restrict__ W1, const float* __restrict__ b1,
    const float* __restrict__ W2, const float* __restrict__ b2,
    const float* __restrict__ WL, const float* __restrict__ bL,
    float* __restrict__ out, int n, int e)
{
    __shared__ float4 sm4[528];   // union: scan ints / MLP weights
    int* si = (int*)sm4;
    const int t = threadIdx.x;
    const int bid = blockIdx.x;
    const int gtid = bid * NT + t;
    const int GSZ = NB * NT;

    // ---- P1: in-degree count (g_deg zero at entry); block 0 folds W2@WL ----
    if (bid == 0) {
        int k = t >> 4, c = t & 15;
        float s = 0.f;
        for (int j = 0; j < 128; j++) s += __ldg(&W2[k * 128 + j]) * __ldg(&WL[j * 16 + c]);
        g_w2l[t] = s;
        if (t < 16) {
            float sb = __ldg(&bL[t]);
            for (int j = 0; j < 128; j++) sb += __ldg(&b2[j]) * __ldg(&WL[j * 16 + t]);
            g_b2l[t] = sb;
        }
    }
    {
        const int4* d4p = (const int4*)(ei + e);
        int ng = e >> 2;   // E divisible by 4
        for (int i = gtid; i < ng; i += GSZ) {
            int4 d4 = __ldg(&d4p[i]);
            atomicAdd(&g_deg[d4.x], 1);
            atomicAdd(&g_deg[d4.y], 1);
            atomicAdd(&g_deg[d4.z], 1);
            atomicAdd(&g_deg[d4.w], 1);
        }
    }
    gsync();

    // ---- P2: dinv + scaled features; block-local scan of PADDED degrees ----
    int myDeg = (gtid < n) ? g_deg[gtid] : 0;
    int myPdeg = (myDeg + 3) & ~3;
    if (gtid < n) {
        float d = rsqrtf((float)(myDeg + 1));   // +1 self-loop (real degree)
        g_dinv[gtid] = d;
        const float4* xr = (const float4*)(x + (size_t)gtid * 16);
        float4* o = (float4*)(g_xs + (size_t)gtid * 16);
#pragma unroll
        for (int r = 0; r < 4; r++) {
            float4 v = __ldg(&xr[r]);
            v.x *= d; v.y *= d; v.z *= d; v.w *= d;
            o[r] = v;
        }
    }
    si[t] = myPdeg;
    __syncthreads();
    for (int o = 1; o < NT; o <<= 1) {
        int a = (t >= o) ? si[t - o] : 0;
        __syncthreads();
        si[t] += a;
        __syncthreads();
    }
    int excl = si[t] - myPdeg;
    if (t == 0) g_bsum[bid] = 0;           // reuse below
    int btot = si[NT - 1];
    if (t == 0) g_bsum[bid] = btot;
    gsync();

    // ---- P3: block offsets; write g_off/g_cur; fill padding sentinels ----
    si[t] = (t < bid) ? g_bsum[t] : 0;
    __syncthreads();
    for (int o2 = 512; o2 > 0; o2 >>= 1) {
        if (t < o2) si[t] += si[t + o2];
        __syncthreads();
    }
    int boff = si[0];
    if (gtid < n) {
        int off = excl + boff;
        g_off[gtid] = off;
        g_cur[gtid] = off;
        for (int p = off + myDeg; p < off + myPdeg; p++) g_csr[p] = n;  // sentinel
        if (gtid == n - 1) g_off[n] = off + myPdeg;
    }
    gsync();

    // ---- P4: CSR fill (int4 edge loads, 4 independent atomics) ----
    {
        const int4* s4p = (const int4*)ei;
        const int4* d4p = (const int4*)(ei + e);
        int ng = e >> 2;
        for (int i = gtid; i < ng; i += GSZ) {
            int4 s4v = __ldg(&s4p[i]);
            int4 d4v = __ldg(&d4p[i]);
            int p0 = atomicAdd(&g_cur[d4v.x], 1);
            int p1 = atomicAdd(&g_cur[d4v.y], 1);
            int p2 = atomicAdd(&g_cur[d4v.z], 1);
            int p3 = atomicAdd(&g_cur[d4v.w], 1);
            g_csr[p0] = s4v.x;
            g_csr[p1] = s4v.y;
            g_csr[p2] = s4v.z;
            g_csr[p3] = s4v.w;
        }
    }
    gsync();

    // ---- P5: layer-1 aggregation (16 floats/node) ----
    for (int w = gtid; w < n * 4; w += GSZ) agg16_item(g_xs, g_a1, nullptr, w);
    gsync();

    // ---- P6: fused MLP  z = (dinv * relu(a1@W1 + b1)) @ W2L ----
    {
        float4* w1t  = sm4;         // [16][16] : W1 row k, col-quad cq
        float4* w2l4 = sm4 + 256;   // [64][4]  : W2L row k, col-quad j
        float4* b1q  = sm4 + 512;   // [16]
        if (t < 256)      w1t[t]        = __ldg(&((const float4*)W1)[t]);
        else if (t < 512) w2l4[t - 256] = ((const float4*)g_w2l)[t - 256];
        else if (t < 528) b1q[t - 512]  = ((const float4*)b1)[t - 512];
        __syncthreads();
        if (gtid < n) {
            const float4* a4 = (const float4*)(g_a1 + (size_t)gtid * 16);
            float a[16];
#pragma unroll
            for (int r = 0; r < 4; r++) {
                float4 v = a4[r];
                a[r * 4 + 0] = v.x; a[r * 4 + 1] = v.y; a[r * 4 + 2] = v.z; a[r * 4 + 3] = v.w;
            }
            float d = g_dinv[gtid];
            float4 z4[4];
#pragma unroll
            for (int j = 0; j < 4; j++) z4[j] = make_float4(0.f, 0.f, 0.f, 0.f);
#pragma unroll
            for (int cq = 0; cq < 16; cq++) {
                float4 h = b1q[cq];
#pragma unroll
                for (int k = 0; k < 16; k++) {
                    float4 w = w1t[k * 16 + cq];
                    float av = a[k];
                    h.x += av * w.x; h.y += av * w.y; h.z += av * w.z; h.w += av * w.w;
                }
                h.x = d * fmaxf(h.x, 0.f);
                h.y = d * fmaxf(h.y, 0.f);
                h.z = d * fmaxf(h.z, 0.f);
                h.w = d * fmaxf(h.w, 0.f);
                int c0 = cq * 4;
                float hv[4] = {h.x, h.y, h.z, h.w};
#pragma unroll
                for (int m = 0; m < 4; m++) {
                    float hm = hv[m];
#pragma unroll
                    for (int j = 0; j < 4; j++) {
                        float4 w = w2l4[(c0 + m) * 4 + j];
                        z4[j].x += hm * w.x; z4[j].y += hm * w.y;
                        z4[j].z += hm * w.z; z4[j].w += hm * w.w;
                    }
                }
            }
            float4* zo = (float4*)(g_z + (size_t)gtid * 16);
#pragma unroll
            for (int j = 0; j < 4; j++) zo[j] = z4[j];
        }
    }
    gsync();

    // ---- P7: layer-2 aggregation + bias -> out; re-zero g_deg for next run ----
    for (int i = gtid; i < n; i += GSZ) g_deg[i] = 0;
    for (int w = gtid; w < n * 4; w += GSZ) agg16_item(g_z, out, g_b2l, w);
}

// ----------------------------------------------------------------
extern "C" void kernel_launch(void* const* d_in, const int* in_sizes, int n_in,
                              void* d_out, int out_size) {
    const float* x  = (const float*)d_in[0];
    const int*   ei = (const int*)d_in[1];
    const float* W1 = (const float*)d_in[2];
    const float* b1 = (const float*)d_in[3];
    const float* W2 = (const float*)d_in[4];
    const float* b2 = (const float*)d_in[5];
    const float* WL = (const float*)d_in[6];
    const float* bL = (const float*)d_in[7];
    float* out = (float*)d_out;

    int n = in_sizes[0] / 16;   // 100000
    int e = in_sizes[1] / 2;    // 1600000

    uber<<<NB, NT>>>(x, ei, W1, b1, W2, b2, WL, bL, out, n, e);
}